// round 12
// baseline (speedup 1.0000x reference)
#include <cuda_runtime.h>
#include <cuda_fp16.h>

#define XSB 144              // x smem row stride, bytes (72 halves)
#define WSB 144              // w smem row stride, bytes
#define CS  264              // epilogue row stride, floats

#define SM_XHI 0
#define SM_W   39168         // x: 272*144
#define SMEM_TOTAL 67584     // max(compute 57600, epilogue 64*264*4)

__device__ __align__(16) __half g_wh[16*64*64];   // [k][f][c] fp16

__global__ void prep_w(const float* w) {
    int i = blockIdx.x*256 + threadIdx.x;         // input layout [f][c][k]
    int k = i & 15, c = (i >> 4) & 63, f = i >> 10;
    g_wh[k*4096 + f*64 + c] = __float2half_rn(w[i]);
}

__device__ __forceinline__ void ldsm4(unsigned* r, unsigned a) {
    asm volatile("ldmatrix.sync.aligned.m8n8.x4.shared.b16 {%0,%1,%2,%3}, [%4];"
        : "=r"(r[0]), "=r"(r[1]), "=r"(r[2]), "=r"(r[3]) : "r"(a));
}
__device__ __forceinline__ void mma16(float* c, const unsigned* a, const unsigned* b) {
    asm volatile("mma.sync.aligned.m16n8k16.row.col.f32.f16.f16.f32 "
        "{%0,%1,%2,%3},{%4,%5,%6,%7},{%8,%9},{%0,%1,%2,%3};"
        : "+f"(c[0]), "+f"(c[1]), "+f"(c[2]), "+f"(c[3])
        : "r"(a[0]), "r"(a[1]), "r"(a[2]), "r"(a[3]), "r"(b[0]), "r"(b[1]));
}
__device__ __forceinline__ void cpa16(unsigned s, const void* g) {
    asm volatile("cp.async.ca.shared.global [%0], [%1], 16;" :: "r"(s), "l"(g));
}

extern __shared__ unsigned char smraw[];

__device__ __forceinline__ void stage_w(unsigned sb, int k, int stage, int tid) {
    unsigned dst = sb + SM_W + stage*(64*WSB);
    #pragma unroll
    for (int r = 0; r < 4; r++) {
        int i = r*128 + tid;                      // 512 chunks of 16B
        int f = i >> 3, seg = i & 7;
        cpa16(dst + f*WSB + seg*16, g_wh + k*4096 + f*64 + seg*8);
    }
    asm volatile("cp.async.commit_group;" ::: "memory");
}

__global__ void __launch_bounds__(128, 2)
conv_main(const float* __restrict__ x, const float* __restrict__ bias, float* __restrict__ out) {
    const int t0 = blockIdx.x * 256;
    const int n  = blockIdx.y;
    const int tid = threadIdx.x;
    unsigned sb;
    asm("{.reg .u64 t; cvta.to.shared.u64 t,%1; cvt.u32.u64 %0,t;}" : "=r"(sb) : "l"(smraw));

    // x window [272 t][64 c], fp16
    const float* xb = x + n*64*4096;
    for (int i = tid; i < 64*272; i += 128) {
        int c = i / 272, t = i - c*272;
        int tg = t0 + t;
        float v = (tg < 4096) ? xb[c*4096 + tg] : 0.f;
        *(__half*)(smraw + SM_XHI + t*XSB + c*2) = __float2half_rn(v);
    }

    const int wid = tid >> 5, lane = tid & 31;    // 4 warps: warp = 64t x 64f
    const unsigned aoff = (lane & 15)*XSB + (lane >> 4)*16;
    const unsigned boff = ((lane & 7) + ((lane >> 4) & 1)*8)*WSB + ((lane >> 3) & 1)*16;
    float acc[4][8][4] = {};

    stage_w(sb, 0, 0, tid);
    asm volatile("cp.async.wait_group 0;" ::: "memory");
    __syncthreads();

    for (int k = 0; k < 16; k++) {
        int s = k & 1;
        if (k < 15) stage_w(sb, k + 1, s ^ 1, tid);
        unsigned xh = sb + SM_XHI + (wid*64 + k)*XSB + aoff;
        unsigned wb = sb + SM_W + s*(64*WSB) + boff;
        #pragma unroll
        for (int cc = 0; cc < 4; cc++) {
            unsigned ah[4][4], bf[4][4];
            #pragma unroll
            for (int m = 0; m < 4; m++) ldsm4(ah[m], xh + m*16*XSB + cc*32);
            #pragma unroll
            for (int q = 0; q < 4; q++) ldsm4(bf[q], wb + q*16*WSB + cc*32);
            #pragma unroll
            for (int nt = 0; nt < 8; nt++) {
                const unsigned* b = &bf[nt >> 1][(nt & 1)*2];
                #pragma unroll
                for (int mt = 0; mt < 4; mt++)
                    mma16(acc[mt][nt], ah[mt], b);
            }
        }
        if (k < 15) asm volatile("cp.async.wait_group 0;" ::: "memory");
        __syncthreads();
    }

    // epilogue: transpose through smem (reuses x region)
    float* csm = (float*)smraw;                   // [64][CS]
    const int g = lane >> 2, tq = lane & 3;
    #pragma unroll
    for (int mt = 0; mt < 4; mt++)
        #pragma unroll
        for (int nt = 0; nt < 8; nt++) {
            int f = nt*8 + 2*tq;
            int r = wid*64 + mt*16 + g;
            csm[f*CS + r]         = acc[mt][nt][0];
            csm[(f+1)*CS + r]     = acc[mt][nt][1];
            csm[f*CS + r + 8]     = acc[mt][nt][2];
            csm[(f+1)*CS + r + 8] = acc[mt][nt][3];
        }
    __syncthreads();
    float* ob = out + n*64*4081;
    for (int i = tid; i < 64*256; i += 128) {
        int f = i >> 8, t = i & 255;
        int tg = t0 + t;
        if (tg < 4081) ob[f*4081 + tg] = csm[f*CS + t] + __ldg(bias + f);
    }
}

extern "C" void kernel_launch(void* const* d_in, const int* in_sizes, int n_in,
                              void* d_out, int out_size) {
    const float* x = (const float*)d_in[0];
    const float* w = (const float*)d_in[1];
    const float* b = (const float*)d_in[2];
    float* out = (float*)d_out;
    (void)in_sizes; (void)n_in; (void)out_size;

    cudaFuncSetAttribute(conv_main, cudaFuncAttributeMaxDynamicSharedMemorySize, SMEM_TOTAL);
    prep_w<<<256, 256>>>(w);
    conv_main<<<dim3(16, 64), 128, SMEM_TOTAL>>>(x, b, out);
}

// round 13
// speedup vs baseline: 1.5687x; 1.5687x over previous
#include <cuda_runtime.h>
#include <cuda_fp16.h>

#define XSB 144              // x smem row stride, bytes (72 halves)
#define CS  132              // epilogue row stride, floats

#define SMEM_TOTAL 20736     // x: 144*144 bytes; epilogue reuses (needs 16896)

// w fragments, mma-register order: [k][cc][q][lane] as uint4 per lane
__device__ __align__(16) unsigned g_wf[16*4*4*128];

__global__ void prep_w(const float* w) {
    int idx = blockIdx.x*256 + threadIdx.x;       // 32768 entries
    int r = idx & 3, lane = (idx >> 2) & 31, q = (idx >> 7) & 3;
    int cc = (idx >> 9) & 3, k = idx >> 11;
    int f = q*16 + (r >> 1)*8 + (lane >> 2);
    int c = cc*16 + (r & 1)*8 + 2*(lane & 3);
    // input layout [f][c][k]
    __half lo = __float2half_rn(w[f*1024 + c*16 + k]);
    __half hi = __float2half_rn(w[f*1024 + (c+1)*16 + k]);
    g_wf[idx] = ((unsigned)__half_as_ushort(hi) << 16) | __half_as_ushort(lo);
}

__device__ __forceinline__ void ldsm4(unsigned* r, unsigned a) {
    asm volatile("ldmatrix.sync.aligned.m8n8.x4.shared.b16 {%0,%1,%2,%3}, [%4];"
        : "=r"(r[0]), "=r"(r[1]), "=r"(r[2]), "=r"(r[3]) : "r"(a));
}
__device__ __forceinline__ void mma16(float* c, const unsigned* a, const unsigned* b) {
    asm volatile("mma.sync.aligned.m16n8k16.row.col.f32.f16.f16.f32 "
        "{%0,%1,%2,%3},{%4,%5,%6,%7},{%8,%9},{%0,%1,%2,%3};"
        : "+f"(c[0]), "+f"(c[1]), "+f"(c[2]), "+f"(c[3])
        : "r"(a[0]), "r"(a[1]), "r"(a[2]), "r"(a[3]), "r"(b[0]), "r"(b[1]));
}

extern __shared__ unsigned char smraw[];

__global__ void __launch_bounds__(128, 4)
conv_main(const float* __restrict__ x, const float* __restrict__ bias, float* __restrict__ out) {
    const int t0 = blockIdx.x * 128;
    const int n  = blockIdx.y;
    const int tid = threadIdx.x;
    unsigned sb;
    asm("{.reg .u64 t; cvta.to.shared.u64 t,%1; cvt.u32.u64 %0,t;}" : "=r"(sb) : "l"(smraw));

    // x window [144 t][64 c], fp16
    const float* xb = x + n*64*4096;
    for (int i = tid; i < 64*144; i += 128) {
        int c = i / 144, t = i - c*144;
        int tg = t0 + t;
        float v = (tg < 4096) ? xb[c*4096 + tg] : 0.f;
        *(__half*)(smraw + t*XSB + c*2) = __float2half_rn(v);
    }

    const int wid = tid >> 5, lane = tid & 31;    // 4 warps: warp = 32t x 64f
    const unsigned aoff = (lane & 15)*XSB + (lane >> 4)*16;
    const uint4* wl = ((const uint4*)g_wf) + lane;
    float acc[2][8][4] = {};

    unsigned bn[16];                              // next-chunk B frags
    #pragma unroll
    for (int q = 0; q < 4; q++) *(uint4*)&bn[q*4] = __ldg(wl + q*32);

    __syncthreads();                              // x ready; no more barriers in loop

    for (int k = 0; k < 16; k++) {
        unsigned xh = sb + (wid*32 + k)*XSB + aoff;
        #pragma unroll
        for (int cc = 0; cc < 4; cc++) {
            unsigned bc[16];
            #pragma unroll
            for (int i = 0; i < 16; i++) bc[i] = bn[i];
            int jn = k*4 + cc + 1;
            if (jn < 64) {
                #pragma unroll
                for (int q = 0; q < 4; q++)
                    *(uint4*)&bn[q*4] = __ldg(wl + (jn*4 + q)*32);
            }
            unsigned ah[2][4];
            ldsm4(ah[0], xh + cc*32);
            ldsm4(ah[1], xh + 16*XSB + cc*32);
            #pragma unroll
            for (int nt = 0; nt < 8; nt++) {
                const unsigned* b = &bc[(nt >> 1)*4 + (nt & 1)*2];
                mma16(acc[0][nt], ah[0], b);
                mma16(acc[1][nt], ah[1], b);
            }
        }
    }

    // epilogue: 2 passes of 32 f through smem (reuses x region)
    float* csm = (float*)smraw;                   // [32][CS]
    float* ob = out + n*64*4081;
    const int g = lane >> 2, tq = lane & 3;
    #pragma unroll
    for (int p = 0; p < 2; p++) {
        __syncthreads();                          // prev readers done
        #pragma unroll
        for (int mt = 0; mt < 2; mt++)
            #pragma unroll
            for (int nq = 0; nq < 4; nq++) {
                int nt = p*4 + nq;
                int fl = nq*8 + 2*tq;
                int r = wid*32 + mt*16 + g;
                csm[fl*CS + r]         = acc[mt][nt][0];
                csm[(fl+1)*CS + r]     = acc[mt][nt][1];
                csm[fl*CS + r + 8]     = acc[mt][nt][2];
                csm[(fl+1)*CS + r + 8] = acc[mt][nt][3];
            }
        __syncthreads();
        for (int i = tid; i < 32*128; i += 128) {
            int f = i >> 7, t = i & 127;
            int tg = t0 + t;
            if (tg < 4081) ob[(p*32 + f)*4081 + tg] = csm[f*CS + t] + __ldg(bias + p*32 + f);
        }
    }
}

extern "C" void kernel_launch(void* const* d_in, const int* in_sizes, int n_in,
                              void* d_out, int out_size) {
    const float* x = (const float*)d_in[0];
    const float* w = (const float*)d_in[1];
    const float* b = (const float*)d_in[2];
    float* out = (float*)d_out;
    (void)in_sizes; (void)n_in; (void)out_size;

    cudaFuncSetAttribute(conv_main, cudaFuncAttributeMaxDynamicSharedMemorySize, SMEM_TOTAL);
    prep_w<<<128, 256>>>(w);
    conv_main<<<dim3(32, 64), 128, SMEM_TOTAL>>>(x, b, out);
}

// round 14
// speedup vs baseline: 1.5994x; 1.0196x over previous
#include <cuda_runtime.h>
#include <cuda_fp16.h>

#define XSB 144              // x smem row stride, bytes (72 halves)
#define CS  132              // epilogue row stride, floats

#define SMEM_TOTAL 20736     // x: 144*144 bytes; epilogue reuses (needs 16896)

// w fragments, mma-register order: [k][cc][q][lane] as uint4 per lane
__device__ __align__(16) unsigned g_wf[16*4*4*128];

__global__ void prep_w(const float* w) {
    int idx = blockIdx.x*256 + threadIdx.x;       // 32768 entries
    int r = idx & 3, lane = (idx >> 2) & 31, q = (idx >> 7) & 3;
    int cc = (idx >> 9) & 3, k = idx >> 11;
    int f = q*16 + (r >> 1)*8 + (lane >> 2);
    int c = cc*16 + (r & 1)*8 + 2*(lane & 3);
    // input layout [f][c][k]
    __half lo = __float2half_rn(w[f*1024 + c*16 + k]);
    __half hi = __float2half_rn(w[f*1024 + (c+1)*16 + k]);
    g_wf[idx] = ((unsigned)__half_as_ushort(hi) << 16) | __half_as_ushort(lo);
}

__device__ __forceinline__ void ldsm4(unsigned* r, unsigned a) {
    asm volatile("ldmatrix.sync.aligned.m8n8.x4.shared.b16 {%0,%1,%2,%3}, [%4];"
        : "=r"(r[0]), "=r"(r[1]), "=r"(r[2]), "=r"(r[3]) : "r"(a));
}
__device__ __forceinline__ void mma16(float* c, const unsigned* a, const unsigned* b) {
    asm volatile("mma.sync.aligned.m16n8k16.row.col.f32.f16.f16.f32 "
        "{%0,%1,%2,%3},{%4,%5,%6,%7},{%8,%9},{%0,%1,%2,%3};"
        : "+f"(c[0]), "+f"(c[1]), "+f"(c[2]), "+f"(c[3])
        : "r"(a[0]), "r"(a[1]), "r"(a[2]), "r"(a[3]), "r"(b[0]), "r"(b[1]));
}

extern __shared__ unsigned char smraw[];

__global__ void __launch_bounds__(128, 4)
conv_main(const float* __restrict__ x, const float* __restrict__ bias, float* __restrict__ out) {
    const int t0 = blockIdx.x * 128;
    const int n  = blockIdx.y;
    const int tid = threadIdx.x;
    unsigned sb;
    asm("{.reg .u64 t; cvta.to.shared.u64 t,%1; cvt.u32.u64 %0,t;}" : "=r"(sb) : "l"(smraw));

    // x window [144 t][64 c], fp16
    const float* xb = x + n*64*4096;
    for (int i = tid; i < 64*144; i += 128) {
        int c = i / 144, t = i - c*144;
        int tg = t0 + t;
        float v = (tg < 4096) ? xb[c*4096 + tg] : 0.f;
        *(__half*)(smraw + t*XSB + c*2) = __float2half_rn(v);
    }

    const int wid = tid >> 5, lane = tid & 31;    // 4 warps: warp = 32t x 64f
    const unsigned aoff = (lane & 15)*XSB + (lane >> 4)*16;
    const uint4* wl = ((const uint4*)g_wf) + lane;
    float acc[2][8][4] = {};

    // parity double-buffer: chunk j uses bb[j&1] (j = k*4+cc, j&1 == cc&1)
    unsigned bb[2][16];
    #pragma unroll
    for (int q = 0; q < 4; q++) *(uint4*)&bb[0][q*4] = __ldg(wl + q*32);
    #pragma unroll
    for (int q = 0; q < 4; q++) *(uint4*)&bb[1][q*4] = __ldg(wl + (4 + q)*32);

    __syncthreads();                              // x ready; no barriers in loop

    for (int k = 0; k < 16; k++) {
        unsigned xh = sb + (wid*32 + k)*XSB + aoff;
        #pragma unroll
        for (int cc = 0; cc < 4; cc++) {
            const int cur = cc & 1;
            unsigned ah[2][4];
            ldsm4(ah[0], xh + cc*32);
            ldsm4(ah[1], xh + 16*XSB + cc*32);
            #pragma unroll
            for (int nt = 0; nt < 8; nt++) {
                const unsigned* b = &bb[cur][(nt >> 1)*4 + (nt & 1)*2];
                mma16(acc[0][nt], ah[0], b);
                mma16(acc[1][nt], ah[1], b);
            }
            int jn = k*4 + cc + 2;                // refill this parity buffer, 2 ahead
            if (jn < 64) {
                #pragma unroll
                for (int q = 0; q < 4; q++)
                    *(uint4*)&bb[cur][q*4] = __ldg(wl + (jn*4 + q)*32);
            }
        }
    }

    // epilogue: 2 passes of 32 f through smem (reuses x region)
    float* csm = (float*)smraw;                   // [32][CS]
    float* ob = out + n*64*4081;
    const int g = lane >> 2, tq = lane & 3;
    #pragma unroll
    for (int p = 0; p < 2; p++) {
        __syncthreads();                          // prev readers done
        #pragma unroll
        for (int mt = 0; mt < 2; mt++)
            #pragma unroll
            for (int nq = 0; nq < 4; nq++) {
                int nt = p*4 + nq;
                int fl = nq*8 + 2*tq;
                int r = wid*32 + mt*16 + g;
                csm[fl*CS + r]         = acc[mt][nt][0];
                csm[(fl+1)*CS + r]     = acc[mt][nt][1];
                csm[fl*CS + r + 8]     = acc[mt][nt][2];
                csm[(fl+1)*CS + r + 8] = acc[mt][nt][3];
            }
        __syncthreads();
        for (int i = tid; i < 32*128; i += 128) {
            int f = i >> 7, t = i & 127;
            int tg = t0 + t;
            if (tg < 4081) ob[(p*32 + f)*4081 + tg] = csm[f*CS + t] + __ldg(bias + p*32 + f);
        }
    }
}

extern "C" void kernel_launch(void* const* d_in, const int* in_sizes, int n_in,
                              void* d_out, int out_size) {
    const float* x = (const float*)d_in[0];
    const float* w = (const float*)d_in[1];
    const float* b = (const float*)d_in[2];
    float* out = (float*)d_out;
    (void)in_sizes; (void)n_in; (void)out_size;

    cudaFuncSetAttribute(conv_main, cudaFuncAttributeMaxDynamicSharedMemorySize, SMEM_TOTAL);
    prep_w<<<128, 256>>>(w);
    conv_main<<<dim3(32, 64), 128, SMEM_TOTAL>>>(x, b, out);
}

// round 15
// speedup vs baseline: 1.6274x; 1.0175x over previous
#include <cuda_runtime.h>
#include <cuda_fp16.h>

#define XSB 144              // x smem row stride, bytes (72 halves)
#define CS  132              // epilogue row stride, floats

#define SMEM_TOTAL 20736     // x: 144*144 bytes; epilogue reuses (needs 16896)

// w fragments, mma-register order: [chunk][q][lane] as uint4 per lane.
// 64 real chunks + 2 pad chunks so distance-2 prefetch needs no bounds check.
__device__ __align__(16) unsigned g_wf[66*4*128];

__global__ void prep_w(const float* w) {
    int idx = blockIdx.x*256 + threadIdx.x;       // 32768 entries
    int r = idx & 3, lane = (idx >> 2) & 31, q = (idx >> 7) & 3;
    int cc = (idx >> 9) & 3, k = idx >> 11;
    int f = q*16 + (r >> 1)*8 + (lane >> 2);
    int c = cc*16 + (r & 1)*8 + 2*(lane & 3);
    // input layout [f][c][k]
    __half lo = __float2half_rn(w[f*1024 + c*16 + k]);
    __half hi = __float2half_rn(w[f*1024 + (c+1)*16 + k]);
    g_wf[idx] = ((unsigned)__half_as_ushort(hi) << 16) | __half_as_ushort(lo);
}

__device__ __forceinline__ void ldsm4(unsigned* r, unsigned a) {
    asm volatile("ldmatrix.sync.aligned.m8n8.x4.shared.b16 {%0,%1,%2,%3}, [%4];"
        : "=r"(r[0]), "=r"(r[1]), "=r"(r[2]), "=r"(r[3]) : "r"(a));
}
__device__ __forceinline__ void mma16(float* c, const unsigned* a, const unsigned* b) {
    asm volatile("mma.sync.aligned.m16n8k16.row.col.f32.f16.f16.f32 "
        "{%0,%1,%2,%3},{%4,%5,%6,%7},{%8,%9},{%0,%1,%2,%3};"
        : "+f"(c[0]), "+f"(c[1]), "+f"(c[2]), "+f"(c[3])
        : "r"(a[0]), "r"(a[1]), "r"(a[2]), "r"(a[3]), "r"(b[0]), "r"(b[1]));
}

extern __shared__ unsigned char smraw[];

__global__ void __launch_bounds__(128, 4)
conv_main(const float* __restrict__ x, const float* __restrict__ bias, float* __restrict__ out) {
    const int t0 = blockIdx.x * 128;
    const int n  = blockIdx.y;
    const int tid = threadIdx.x;
    unsigned sb;
    asm("{.reg .u64 t; cvta.to.shared.u64 t,%1; cvt.u32.u64 %0,t;}" : "=r"(sb) : "l"(smraw));

    // x window [144 t][64 c], fp16
    const float* xb = x + n*64*4096;
    for (int i = tid; i < 64*144; i += 128) {
        int c = i / 144, t = i - c*144;
        int tg = t0 + t;
        float v = (tg < 4096) ? xb[c*4096 + tg] : 0.f;
        *(__half*)(smraw + t*XSB + c*2) = __float2half_rn(v);
    }

    const int wid = tid >> 5, lane = tid & 31;    // 4 warps: warp = 32t x 64f
    const unsigned aoff = (lane & 15)*XSB + (lane >> 4)*16;
    const uint4* wp = ((const uint4*)g_wf) + lane;
    float acc[2][8][4] = {};

    // B parity double-buffer (chunk j uses bb[j&1]); prefetch distance 2
    unsigned bb[2][16];
    #pragma unroll
    for (int q = 0; q < 4; q++) *(uint4*)&bb[0][q*4] = __ldg(wp + q*32);
    wp += 128;
    #pragma unroll
    for (int q = 0; q < 4; q++) *(uint4*)&bb[1][q*4] = __ldg(wp + q*32);
    wp += 128;                                    // wp -> chunk 2

    __syncthreads();                              // x ready; no barriers in loop

    // A parity double-buffer (distance 1); preload chunk 0
    unsigned ah[2][2][4];
    {
        unsigned a0 = sb + wid*32*XSB + aoff;
        ldsm4(ah[0][0], a0);
        ldsm4(ah[0][1], a0 + 16*XSB);
    }

    for (int k = 0; k < 16; k++) {
        unsigned xh = sb + (wid*32 + k)*XSB + aoff;
        #pragma unroll
        for (int cc = 0; cc < 4; cc++) {
            const int cur = cc & 1, nxt = cur ^ 1;
            // prefetch next chunk's A (at (15,3) this reads halo rows — in bounds, unused)
            unsigned an = (cc < 3) ? (xh + (cc + 1)*32) : (xh + XSB);
            ldsm4(ah[nxt][0], an);
            ldsm4(ah[nxt][1], an + 16*XSB);
            // 16 HMMA on previously-loaded fragments
            #pragma unroll
            for (int nt = 0; nt < 8; nt++) {
                const unsigned* b = &bb[cur][(nt >> 1)*4 + (nt & 1)*2];
                mma16(acc[0][nt], ah[cur][0], b);
                mma16(acc[1][nt], ah[cur][1], b);
            }
            // refill this parity's B, 2 chunks ahead (pad chunks make it branch-free)
            #pragma unroll
            for (int q = 0; q < 4; q++)
                *(uint4*)&bb[cur][q*4] = __ldg(wp + q*32);
            wp += 128;
        }
    }

    // epilogue: 2 passes of 32 f through smem (reuses x region)
    float* csm = (float*)smraw;                   // [32][CS]
    float* ob = out + n*64*4081;
    const int g = lane >> 2, tq = lane & 3;
    #pragma unroll
    for (int p = 0; p < 2; p++) {
        __syncthreads();                          // prev readers done
        #pragma unroll
        for (int mt = 0; mt < 2; mt++)
            #pragma unroll
            for (int nq = 0; nq < 4; nq++) {
                int nt = p*4 + nq;
                int fl = nq*8 + 2*tq;
                int r = wid*32 + mt*16 + g;
                csm[fl*CS + r]         = acc[mt][nt][0];
                csm[(fl+1)*CS + r]     = acc[mt][nt][1];
                csm[fl*CS + r + 8]     = acc[mt][nt][2];
                csm[(fl+1)*CS + r + 8] = acc[mt][nt][3];
            }
        __syncthreads();
        for (int i = tid; i < 32*128; i += 128) {
            int f = i >> 7, t = i & 127;
            int tg = t0 + t;
            if (tg < 4081) ob[(p*32 + f)*4081 + tg] = csm[f*CS + t] + __ldg(bias + p*32 + f);
        }
    }
}

extern "C" void kernel_launch(void* const* d_in, const int* in_sizes, int n_in,
                              void* d_out, int out_size) {
    const float* x = (const float*)d_in[0];
    const float* w = (const float*)d_in[1];
    const float* b = (const float*)d_in[2];
    float* out = (float*)d_out;
    (void)in_sizes; (void)n_in; (void)out_size;

    cudaFuncSetAttribute(conv_main, cudaFuncAttributeMaxDynamicSharedMemorySize, SMEM_TOTAL);
    prep_w<<<128, 256>>>(w);
    conv_main<<<dim3(32, 64), 128, SMEM_TOTAL>>>(x, b, out);
}

// round 16
// speedup vs baseline: 1.6595x; 1.0198x over previous
#include <cuda_runtime.h>
#include <cuda_fp16.h>

#define XSB 144              // x smem row stride, bytes (72 halves)
#define CS  132              // epilogue row stride, floats

#define SMEM_TOTAL 20736     // x: 144*144 bytes; epilogue reuses (needs 16896)

// w fragments, mma-register order: [chunk][q][lane] as uint4 per lane.
// 64 real chunks + 2 pad chunks so distance-2 prefetch needs no bounds check.
__device__ __align__(16) unsigned g_wf[66*4*128];

__global__ void prep_w(const float* w) {
    int idx = blockIdx.x*256 + threadIdx.x;       // 32768 entries
    int r = idx & 3, lane = (idx >> 2) & 31, q = (idx >> 7) & 3;
    int cc = (idx >> 9) & 3, k = idx >> 11;
    int f = q*16 + (r >> 1)*8 + (lane >> 2);
    int c = cc*16 + (r & 1)*8 + 2*(lane & 3);
    // input layout [f][c][k]
    __half lo = __float2half_rn(w[f*1024 + c*16 + k]);
    __half hi = __float2half_rn(w[f*1024 + (c+1)*16 + k]);
    g_wf[idx] = ((unsigned)__half_as_ushort(hi) << 16) | __half_as_ushort(lo);
}

__device__ __forceinline__ void ldsm4(unsigned* r, unsigned a) {
    asm volatile("ldmatrix.sync.aligned.m8n8.x4.shared.b16 {%0,%1,%2,%3}, [%4];"
        : "=r"(r[0]), "=r"(r[1]), "=r"(r[2]), "=r"(r[3]) : "r"(a));
}
__device__ __forceinline__ void mma16(float* c, const unsigned* a, const unsigned* b) {
    asm volatile("mma.sync.aligned.m16n8k16.row.col.f32.f16.f16.f32 "
        "{%0,%1,%2,%3},{%4,%5,%6,%7},{%8,%9},{%0,%1,%2,%3};"
        : "+f"(c[0]), "+f"(c[1]), "+f"(c[2]), "+f"(c[3])
        : "r"(a[0]), "r"(a[1]), "r"(a[2]), "r"(a[3]), "r"(b[0]), "r"(b[1]));
}

extern __shared__ unsigned char smraw[];

__global__ void __launch_bounds__(256, 3)
conv_main(const float* __restrict__ x, const float* __restrict__ bias, float* __restrict__ out) {
    const int t0 = blockIdx.x * 128;
    const int n  = blockIdx.y;
    const int tid = threadIdx.x;
    unsigned sb;
    asm("{.reg .u64 t; cvta.to.shared.u64 t,%1; cvt.u32.u64 %0,t;}" : "=r"(sb) : "l"(smraw));

    // x window [144 t][64 c], fp16
    const float* xb = x + n*64*4096;
    for (int i = tid; i < 64*144; i += 256) {
        int c = i / 144, t = i - c*144;
        int tg = t0 + t;
        float v = (tg < 4096) ? xb[c*4096 + tg] : 0.f;
        *(__half*)(smraw + t*XSB + c*2) = __float2half_rn(v);
    }

    const int wid = tid >> 5, lane = tid & 31;
    const int wm = wid >> 1, wn = wid & 1;        // 8 warps: 4(t) x 2(f); warp = 32t x 32f
    const unsigned aoff = (lane & 15)*XSB + (lane >> 4)*16;
    // warp's B records: q in {wn*2, wn*2+1}
    const uint4* wp = ((const uint4*)g_wf) + wn*64 + lane;
    float acc[2][4][4] = {};

    // B parity double-buffer (chunk j uses bb[j&1]); prefetch distance 2
    unsigned bb[2][8];
    #pragma unroll
    for (int q = 0; q < 2; q++) *(uint4*)&bb[0][q*4] = __ldg(wp + q*32);
    wp += 128;
    #pragma unroll
    for (int q = 0; q < 2; q++) *(uint4*)&bb[1][q*4] = __ldg(wp + q*32);
    wp += 128;                                    // wp -> chunk 2

    __syncthreads();                              // x ready; no barriers in loop

    for (int k = 0; k < 16; k++) {
        unsigned xh = sb + (wm*32 + k)*XSB + aoff;
        #pragma unroll
        for (int cc = 0; cc < 4; cc++) {
            const int cur = cc & 1;
            unsigned ah[2][4];
            ldsm4(ah[0], xh + cc*32);
            ldsm4(ah[1], xh + 16*XSB + cc*32);
            #pragma unroll
            for (int nt = 0; nt < 4; nt++) {
                const unsigned* b = &bb[cur][(nt >> 1)*4 + (nt & 1)*2];
                mma16(acc[0][nt], ah[0], b);
                mma16(acc[1][nt], ah[1], b);
            }
            // refill this parity's B, 2 chunks ahead (pad chunks: branch-free)
            #pragma unroll
            for (int q = 0; q < 2; q++)
                *(uint4*)&bb[cur][q*4] = __ldg(wp + q*32);
            wp += 128;
        }
    }

    // epilogue: 2 passes of 32 f through smem (reuses x region)
    float* csm = (float*)smraw;                   // [32][CS]
    float* ob = out + n*64*4081;
    const int g = lane >> 2, tq = lane & 3;
    #pragma unroll
    for (int p = 0; p < 2; p++) {
        __syncthreads();                          // prev readers done
        if (wn == p) {
            #pragma unroll
            for (int mt = 0; mt < 2; mt++)
                #pragma unroll
                for (int nt = 0; nt < 4; nt++) {
                    int fl = nt*8 + 2*tq;
                    int r = wm*32 + mt*16 + g;
                    csm[fl*CS + r]         = acc[mt][nt][0];
                    csm[(fl+1)*CS + r]     = acc[mt][nt][1];
                    csm[fl*CS + r + 8]     = acc[mt][nt][2];
                    csm[(fl+1)*CS + r + 8] = acc[mt][nt][3];
                }
        }
        __syncthreads();
        for (int i = tid; i < 32*128; i += 256) {
            int f = i >> 7, t = i & 127;
            int tg = t0 + t;
            if (tg < 4081) ob[(p*32 + f)*4081 + tg] = csm[f*CS + t] + __ldg(bias + p*32 + f);
        }
    }
}

extern "C" void kernel_launch(void* const* d_in, const int* in_sizes, int n_in,
                              void* d_out, int out_size) {
    const float* x = (const float*)d_in[0];
    const float* w = (const float*)d_in[1];
    const float* b = (const float*)d_in[2];
    float* out = (float*)d_out;
    (void)in_sizes; (void)n_in; (void)out_size;

    cudaFuncSetAttribute(conv_main, cudaFuncAttributeMaxDynamicSharedMemorySize, SMEM_TOTAL);
    prep_w<<<128, 256>>>(w);
    conv_main<<<dim3(32, 64), 256, SMEM_TOTAL>>>(x, b, out);
}